// round 12
// baseline (speedup 1.0000x reference)
#include <cuda_runtime.h>
#include <cstdint>

#define NMAX 100000
#define EMAX 1000000
#define DD 128

// Scratch (allocation-free rule: __device__ globals)
__device__ float g_x[(size_t)NMAX * DD];   // h_in @ W
__device__ float g_dis[NMAX];
__device__ int   g_cnt[NMAX];              // in-degree (no self loop)
__device__ int   g_fill[NMAX];
__device__ int   g_row[NMAX];              // CSR row start
__device__ int   g_part[1024];             // scan partials
__device__ int   g_csr[EMAX];              // src per (dst-sorted) edge

// ---------------------------------------------------------------------------
__global__ void zero_kernel(int N) {
    int i = blockIdx.x * blockDim.x + threadIdx.x;
    if (i < N) { g_cnt[i] = 0; g_fill[i] = 0; }
}

__global__ void count_kernel(const int* __restrict__ ei, int E) {
    int e = blockIdx.x * blockDim.x + threadIdx.x;
    if (e < E) {
        int d = ei[E + e];
        if ((unsigned)d < NMAX) atomicAdd(&g_cnt[d], 1);
    }
}

// ---------------- shfl-based exclusive scan over g_cnt -> g_row ------------
__global__ void scan_block(int N) {
    __shared__ int ws[32];
    int tid  = threadIdx.x;
    int lane = tid & 31;
    int wid  = tid >> 5;
    int i = blockIdx.x * 1024 + tid;
    int orig = (i < N) ? g_cnt[i] : 0;
    int v = orig;
    #pragma unroll
    for (int off = 1; off < 32; off <<= 1) {
        int t = __shfl_up_sync(0xFFFFFFFFu, v, off);
        if (lane >= off) v += t;
    }
    if (lane == 31) ws[wid] = v;
    __syncthreads();
    if (wid == 0) {
        int u = ws[lane];
        #pragma unroll
        for (int off = 1; off < 32; off <<= 1) {
            int t = __shfl_up_sync(0xFFFFFFFFu, u, off);
            if (lane >= off) u += t;
        }
        ws[lane] = u;
    }
    __syncthreads();
    int base = (wid > 0) ? ws[wid - 1] : 0;
    if (i < N) g_row[i] = base + v - orig;             // exclusive
    if (tid == 1023) g_part[blockIdx.x] = base + v;    // block total
}

__global__ void scan_part(int nb) {
    __shared__ int ws[32];
    int tid  = threadIdx.x;
    int lane = tid & 31;
    int wid  = tid >> 5;
    int orig = (tid < nb) ? g_part[tid] : 0;
    int v = orig;
    #pragma unroll
    for (int off = 1; off < 32; off <<= 1) {
        int t = __shfl_up_sync(0xFFFFFFFFu, v, off);
        if (lane >= off) v += t;
    }
    if (lane == 31) ws[wid] = v;
    __syncthreads();
    if (wid == 0) {
        int u = ws[lane];
        #pragma unroll
        for (int off = 1; off < 32; off <<= 1) {
            int t = __shfl_up_sync(0xFFFFFFFFu, u, off);
            if (lane >= off) u += t;
        }
        ws[lane] = u;
    }
    __syncthreads();
    int base = (wid > 0) ? ws[wid - 1] : 0;
    if (tid < nb) g_part[tid] = base + v - orig;       // exclusive
}

// scan_add + dis fused
__global__ void scan_add(int N) {
    int i = blockIdx.x * 1024 + threadIdx.x;
    if (i < N) {
        g_row[i] += g_part[blockIdx.x];
        g_dis[i] = rsqrtf((float)g_cnt[i] + 1.0f);     // +1 self loop
    }
}

__global__ void fill_kernel(const int* __restrict__ ei, int E) {
    int e = blockIdx.x * blockDim.x + threadIdx.x;
    if (e < E) {
        int s = ei[e];
        int d = ei[E + e];
        if ((unsigned)s >= NMAX || (unsigned)d >= NMAX) return;
        int slot = g_row[d] + atomicAdd(&g_fill[d], 1);
        if (slot < EMAX) g_csr[slot] = s;
    }
}

// ---------------------------------------------------------------------------
// GEMM with packed fp32 FFMA2 (fma.rn.f32x2): 2 FMAs per fma-pipe issue.
// A tile stored TRANSPOSED in smem: At[k][r] (pad 66) so a row-pair is one
// aligned LDS.64 broadcast. Accumulators packed across rows. W read via L1.
// ---------------------------------------------------------------------------
#define TILE_ROWS 64
#define ATPAD 66

__device__ __forceinline__ unsigned long long dup2(float w) {
    unsigned long long r;
    asm("mov.b64 %0, {%1, %1};" : "=l"(r) : "r"(__float_as_uint(w)));
    return r;
}
__device__ __forceinline__ void ffma2(unsigned long long& acc,
                                      unsigned long long a,
                                      unsigned long long b) {
    asm("fma.rn.f32x2 %0, %1, %2, %0;" : "+l"(acc) : "l"(a), "l"(b));
}

__global__ void __launch_bounds__(256) gemm_kernel(
    const float* __restrict__ h, const float* __restrict__ W, int N)
{
    __shared__ __align__(16) float At[DD * ATPAD];   // [k][r], ~33 KB

    int tid  = threadIdx.x;
    int lane = tid & 31;
    int wrp  = tid >> 5;

    int ntiles = (N + TILE_ROWS - 1) / TILE_ROWS;
    for (int t = blockIdx.x; t < ntiles; t += gridDim.x) {
        int row0 = t * TILE_ROWS;

        // Load + transpose A tile: idx -> (row = idx&63, kq = idx>>6)
        // Warp lanes map to consecutive rows -> conflict-free STS.
        for (int idx = tid; idx < TILE_ROWS * 32; idx += 256) {
            int row = idx & 63;
            int kq  = idx >> 6;          // float4 index along k
            int grow = row0 + row;
            float4 v = (grow < N) ? ((const float4*)h)[(size_t)grow * 32 + kq]
                                  : make_float4(0.f, 0.f, 0.f, 0.f);
            At[(4 * kq + 0) * ATPAD + row] = v.x;
            At[(4 * kq + 1) * ATPAD + row] = v.y;
            At[(4 * kq + 2) * ATPAD + row] = v.z;
            At[(4 * kq + 3) * ATPAD + row] = v.w;
        }
        __syncthreads();

        // acc[p][c]: rows (2p, 2p+1), col cbase+c  (8 rows x 4 cols)
        unsigned long long acc[4][4];
        #pragma unroll
        for (int p = 0; p < 4; p++)
            #pragma unroll
            for (int c = 0; c < 4; c++) acc[p][c] = 0ull;

        int rbase = wrp * 8;
        int cbase = lane * 4;
        const float* Wc = W + cbase;

        #pragma unroll 4
        for (int k = 0; k < DD; k++) {
            unsigned long long ap[4];
            const float* atk = &At[k * ATPAD + rbase];
            #pragma unroll
            for (int p = 0; p < 4; p++)
                ap[p] = *(const unsigned long long*)(atk + 2 * p);

            float4 w4 = __ldg((const float4*)&Wc[k * DD]);
            unsigned long long wd0 = dup2(w4.x);
            unsigned long long wd1 = dup2(w4.y);
            unsigned long long wd2 = dup2(w4.z);
            unsigned long long wd3 = dup2(w4.w);

            #pragma unroll
            for (int p = 0; p < 4; p++) {
                ffma2(acc[p][0], ap[p], wd0);
                ffma2(acc[p][1], ap[p], wd1);
                ffma2(acc[p][2], ap[p], wd2);
                ffma2(acc[p][3], ap[p], wd3);
            }
        }

        // Unpack + store: pair p holds rows 2p (lo) and 2p+1 (hi)
        #pragma unroll
        for (int p = 0; p < 4; p++) {
            int r0 = row0 + rbase + 2 * p;
            if (r0 < N) {
                float4 o;
                o.x = __uint_as_float((unsigned)(acc[p][0]));
                o.y = __uint_as_float((unsigned)(acc[p][1]));
                o.z = __uint_as_float((unsigned)(acc[p][2]));
                o.w = __uint_as_float((unsigned)(acc[p][3]));
                *(float4*)&g_x[(size_t)r0 * DD + cbase] = o;
            }
            if (r0 + 1 < N) {
                float4 o;
                o.x = __uint_as_float((unsigned)(acc[p][0] >> 32));
                o.y = __uint_as_float((unsigned)(acc[p][1] >> 32));
                o.z = __uint_as_float((unsigned)(acc[p][2] >> 32));
                o.w = __uint_as_float((unsigned)(acc[p][3] >> 32));
                *(float4*)&g_x[(size_t)(r0 + 1) * DD + cbase] = o;
            }
        }
        __syncthreads();
    }
}

// ---------------------------------------------------------------------------
// Fused aggregate + epilogue: one warp per node. (L2-gather bound)
// ---------------------------------------------------------------------------
__global__ void agg_kernel(float* __restrict__ out,
                           const float* __restrict__ bvec,
                           const float* __restrict__ prelu_a,
                           const float* __restrict__ gamma,
                           const float* __restrict__ beta,
                           int N)
{
    int gtid = blockIdx.x * blockDim.x + threadIdx.x;
    int i    = gtid >> 5;
    int lane = gtid & 31;
    if (i >= N) return;

    float di    = g_dis[i];
    int   start = g_row[i];
    int   len   = g_cnt[i];

    // self loop
    float4 xv = ((const float4*)g_x)[(size_t)i * 32 + lane];
    float  d2 = di * di;
    float a0 = d2 * xv.x, a1 = d2 * xv.y, a2 = d2 * xv.z, a3 = d2 * xv.w;

    for (int k = 0; k < len; k++) {
        int   s    = g_csr[start + k];
        float norm = di * g_dis[s];
        float4 v = ((const float4*)g_x)[(size_t)s * 32 + lane];
        a0 = fmaf(norm, v.x, a0);
        a1 = fmaf(norm, v.y, a1);
        a2 = fmaf(norm, v.z, a2);
        a3 = fmaf(norm, v.w, a3);
    }

    float4 bv = ((const float4*)bvec)[lane];
    float slope = prelu_a[0];

    float h0 = a0 + bv.x, h1 = a1 + bv.y, h2 = a2 + bv.z, h3 = a3 + bv.w;
    h0 = (h0 >= 0.f) ? h0 : slope * h0;
    h1 = (h1 >= 0.f) ? h1 : slope * h1;
    h2 = (h2 >= 0.f) ? h2 : slope * h2;
    h3 = (h3 >= 0.f) ? h3 : slope * h3;

    float sum = h0 + h1 + h2 + h3;
    float sq  = h0*h0 + h1*h1 + h2*h2 + h3*h3;
    #pragma unroll
    for (int m = 16; m > 0; m >>= 1) {
        sum += __shfl_xor_sync(0xFFFFFFFFu, sum, m);
        sq  += __shfl_xor_sync(0xFFFFFFFFu, sq,  m);
    }
    float mu   = sum * (1.0f / 128.0f);
    float var  = sq * (1.0f / 128.0f) - mu * mu;
    float rstd = rsqrtf(var + 1e-5f);

    float4 gm = ((const float4*)gamma)[lane];
    float4 be = ((const float4*)beta)[lane];

    float4 o;
    o.x = (h0 - mu) * rstd * gm.x + be.x;
    o.y = (h1 - mu) * rstd * gm.y + be.y;
    o.z = (h2 - mu) * rstd * gm.z + be.z;
    o.w = (h3 - mu) * rstd * gm.w + be.w;

    ((float4*)out)[(size_t)i * 32 + lane] = o;
}

// ---------------------------------------------------------------------------
extern "C" void kernel_launch(void* const* d_in, const int* in_sizes, int n_in,
                              void* d_out, int out_size)
{
    const float* h_in  = (const float*)d_in[0];
    const int*   ei    = (const int*)d_in[1];     // int32 (JAX default x64 off)
    const float* W     = (const float*)d_in[2];
    const float* bvec  = (const float*)d_in[3];
    const float* pa    = (const float*)d_in[4];
    const float* gamma = (const float*)d_in[5];
    const float* beta  = (const float*)d_in[6];
    float*       out   = (float*)d_out;

    int N = in_sizes[0] / DD;
    int E = in_sizes[1] / 2;
    if (N > NMAX) N = NMAX;
    if (E > EMAX) E = EMAX;

    int nb1024 = (N + 1023) / 1024;

    // CSR build
    zero_kernel<<<(N + 255) / 256, 256>>>(N);
    count_kernel<<<(E + 255) / 256, 256>>>(ei, E);
    scan_block<<<nb1024, 1024>>>(N);
    scan_part<<<1, 1024>>>(nb1024);
    scan_add<<<nb1024, 1024>>>(N);
    fill_kernel<<<(E + 255) / 256, 256>>>(ei, E);

    // GEMM (FFMA2)
    gemm_kernel<<<296, 256>>>(h_in, W, N);

    // Fused aggregate + bias + PReLU + LayerNorm
    {
        int threads = N * 32;
        agg_kernel<<<(threads + 255) / 256, 256>>>(out, bvec, pa, gamma, beta, N);
    }
}

// round 16
// speedup vs baseline: 1.4791x; 1.4791x over previous
#include <cuda_runtime.h>
#include <cuda_bf16.h>
#include <cstdint>

#define NMAX 100000
#define EMAX 1000000
#define DD 128

// Scratch (allocation-free rule: __device__ globals)
__device__ float g_x[(size_t)NMAX * DD];   // h_in @ W
__device__ float g_dis[NMAX];
__device__ int   g_cnt[NMAX];              // in-degree (no self loop)
__device__ int   g_fill[NMAX];
__device__ int   g_row[NMAX];              // CSR row start
__device__ int   g_part[1024];             // scan partials
__device__ int   g_csr[EMAX];              // src per (dst-sorted) edge

// ---------------------------------------------------------------------------
__global__ void zero_kernel(int N) {
    int i = blockIdx.x * blockDim.x + threadIdx.x;
    if (i < N) { g_cnt[i] = 0; g_fill[i] = 0; }
}

__global__ void count_kernel(const int* __restrict__ ei, int E) {
    int e = blockIdx.x * blockDim.x + threadIdx.x;
    if (e < E) {
        int d = ei[E + e];
        if ((unsigned)d < NMAX) atomicAdd(&g_cnt[d], 1);
    }
}

// ---------------- shfl-based exclusive scan over g_cnt -> g_row ------------
__global__ void scan_block(int N) {
    __shared__ int ws[32];
    int tid  = threadIdx.x;
    int lane = tid & 31;
    int wid  = tid >> 5;
    int i = blockIdx.x * 1024 + tid;
    int orig = (i < N) ? g_cnt[i] : 0;
    int v = orig;
    #pragma unroll
    for (int off = 1; off < 32; off <<= 1) {
        int t = __shfl_up_sync(0xFFFFFFFFu, v, off);
        if (lane >= off) v += t;
    }
    if (lane == 31) ws[wid] = v;
    __syncthreads();
    if (wid == 0) {
        int u = ws[lane];
        #pragma unroll
        for (int off = 1; off < 32; off <<= 1) {
            int t = __shfl_up_sync(0xFFFFFFFFu, u, off);
            if (lane >= off) u += t;
        }
        ws[lane] = u;
    }
    __syncthreads();
    int base = (wid > 0) ? ws[wid - 1] : 0;
    if (i < N) g_row[i] = base + v - orig;             // exclusive
    if (tid == 1023) g_part[blockIdx.x] = base + v;    // block total
}

__global__ void scan_part(int nb) {
    __shared__ int ws[32];
    int tid  = threadIdx.x;
    int lane = tid & 31;
    int wid  = tid >> 5;
    int orig = (tid < nb) ? g_part[tid] : 0;
    int v = orig;
    #pragma unroll
    for (int off = 1; off < 32; off <<= 1) {
        int t = __shfl_up_sync(0xFFFFFFFFu, v, off);
        if (lane >= off) v += t;
    }
    if (lane == 31) ws[wid] = v;
    __syncthreads();
    if (wid == 0) {
        int u = ws[lane];
        #pragma unroll
        for (int off = 1; off < 32; off <<= 1) {
            int t = __shfl_up_sync(0xFFFFFFFFu, u, off);
            if (lane >= off) u += t;
        }
        ws[lane] = u;
    }
    __syncthreads();
    int base = (wid > 0) ? ws[wid - 1] : 0;
    if (tid < nb) g_part[tid] = base + v - orig;       // exclusive
}

__global__ void scan_add(int N) {
    int i = blockIdx.x * 1024 + threadIdx.x;
    if (i < N) {
        g_row[i] += g_part[blockIdx.x];
        g_dis[i] = rsqrtf((float)g_cnt[i] + 1.0f);     // +1 self loop
    }
}

__global__ void fill_kernel(const int* __restrict__ ei, int E) {
    int e = blockIdx.x * blockDim.x + threadIdx.x;
    if (e < E) {
        int s = ei[e];
        int d = ei[E + e];
        if ((unsigned)s >= NMAX || (unsigned)d >= NMAX) return;
        int slot = g_row[d] + atomicAdd(&g_fill[d], 1);
        if (slot < EMAX) g_csr[slot] = s;
    }
}

// ===========================================================================
// HMMA (mma.sync, baseline PTX - no 'a'-suffix features) bf16-split GEMM:
// g_x = h_in @ W with D = Ah*Wh + Ah*Wl + Al*Wh accumulated in fp32.
// Per block: 256 thr, tile 128 rows x 128 cols; warp owns 16 rows.
// Smem: Ah/Al [128][136] bf16, Wh/Wl [128][136] bf16 (row pad 272B ->
// ldmatrix conflict-free). W converted once per persistent block.
// ===========================================================================
#define APAD 136
#define TSTRIDE (APAD * 2)                  // 272 bytes per row
#define SM_AH 0
#define SM_AL (128 * TSTRIDE)
#define SM_WH (2 * 128 * TSTRIDE)
#define SM_WL (3 * 128 * TSTRIDE)
#define SMEM_DYN (4 * 128 * TSTRIDE)        // 139264 B

__device__ __forceinline__ uint32_t smem_u32(const void* p) {
    uint32_t a;
    asm("{ .reg .u64 t; cvta.to.shared.u64 t, %1; cvt.u32.u64 %0, t; }"
        : "=r"(a) : "l"(p));
    return a;
}

__device__ __forceinline__ void ldsm_x4(uint32_t& r0, uint32_t& r1,
                                        uint32_t& r2, uint32_t& r3,
                                        uint32_t addr) {
    asm volatile("ldmatrix.sync.aligned.m8n8.x4.shared.b16 {%0,%1,%2,%3}, [%4];"
                 : "=r"(r0), "=r"(r1), "=r"(r2), "=r"(r3) : "r"(addr));
}
__device__ __forceinline__ void ldsm_x2t(uint32_t& r0, uint32_t& r1,
                                         uint32_t addr) {
    asm volatile("ldmatrix.sync.aligned.m8n8.x2.trans.shared.b16 {%0,%1}, [%2];"
                 : "=r"(r0), "=r"(r1) : "r"(addr));
}
__device__ __forceinline__ void mma16816(float* d, const uint32_t* a,
                                         uint32_t b0, uint32_t b1) {
    asm volatile(
        "mma.sync.aligned.m16n8k16.row.col.f32.bf16.bf16.f32 "
        "{%0,%1,%2,%3}, {%4,%5,%6,%7}, {%8,%9}, {%0,%1,%2,%3};"
        : "+f"(d[0]), "+f"(d[1]), "+f"(d[2]), "+f"(d[3])
        : "r"(a[0]), "r"(a[1]), "r"(a[2]), "r"(a[3]), "r"(b0), "r"(b1));
}

// split one float4 into hi/lo bf16 pairs packed as uint2
__device__ __forceinline__ void split4(float4 v, uint2& hp, uint2& lp) {
    __nv_bfloat16 hx = __float2bfloat16_rn(v.x);
    __nv_bfloat16 hy = __float2bfloat16_rn(v.y);
    __nv_bfloat16 hz = __float2bfloat16_rn(v.z);
    __nv_bfloat16 hw = __float2bfloat16_rn(v.w);
    __nv_bfloat162 h01, h23, l01, l23;
    h01.x = hx; h01.y = hy; h23.x = hz; h23.y = hw;
    l01.x = __float2bfloat16_rn(v.x - __bfloat162float(hx));
    l01.y = __float2bfloat16_rn(v.y - __bfloat162float(hy));
    l23.x = __float2bfloat16_rn(v.z - __bfloat162float(hz));
    l23.y = __float2bfloat16_rn(v.w - __bfloat162float(hw));
    hp.x = *(uint32_t*)&h01; hp.y = *(uint32_t*)&h23;
    lp.x = *(uint32_t*)&l01; lp.y = *(uint32_t*)&l23;
}

__global__ void __launch_bounds__(256) gemm_tc(
    const float* __restrict__ h, const float* __restrict__ W, int N)
{
    extern __shared__ char sm[];
    int tid  = threadIdx.x;
    int lane = tid & 31;
    int wid  = tid >> 5;

    uint32_t sbase = smem_u32(sm);

    // ---- Convert W[k][n] -> Wh/Wl [k][n] bf16 once per block
    for (int idx = tid; idx < DD * 32; idx += 256) {
        int k  = idx >> 5;
        int nq = idx & 31;
        float4 w = ((const float4*)W)[k * 32 + nq];
        uint2 hp, lp;
        split4(w, hp, lp);
        *(uint2*)(sm + SM_WH + k * TSTRIDE + nq * 8) = hp;
        *(uint2*)(sm + SM_WL + k * TSTRIDE + nq * 8) = lp;
    }
    __syncthreads();

    // per-lane ldmatrix addresses (row part)
    int lrow = lane & 15;                       // A/B row within fragment
    int lcol = (lane >> 4) * 16;                // A: 16B column half

    int ntiles = (N + 127) / 128;
    for (int t = blockIdx.x; t < ntiles; t += gridDim.x) {
        int row0 = t * 128;

        // ---- load + split A tile: [128][136] hi/lo
        for (int idx = tid; idx < 128 * 32; idx += 256) {
            int r  = idx >> 5;
            int kq = idx & 31;
            int grow = row0 + r;
            float4 v = (grow < N) ? ((const float4*)h)[(size_t)grow * 32 + kq]
                                  : make_float4(0.f, 0.f, 0.f, 0.f);
            uint2 hp, lp;
            split4(v, hp, lp);
            *(uint2*)(sm + SM_AH + r * TSTRIDE + kq * 8) = hp;
            *(uint2*)(sm + SM_AL + r * TSTRIDE + kq * 8) = lp;
        }
        __syncthreads();

        float acc[16][4];
        #pragma unroll
        for (int n = 0; n < 16; n++)
            #pragma unroll
            for (int j = 0; j < 4; j++) acc[n][j] = 0.f;

        int wr = wid * 16;                      // warp's row base in tile

        #pragma unroll
        for (int kt = 0; kt < 8; kt++) {
            // A fragments (16x16) hi & lo
            uint32_t ah[4], al[4];
            uint32_t a_off = (wr + lrow) * TSTRIDE + kt * 32 + lcol;
            ldsm_x4(ah[0], ah[1], ah[2], ah[3], sbase + SM_AH + a_off);
            ldsm_x4(al[0], al[1], al[2], al[3], sbase + SM_AL + a_off);

            #pragma unroll
            for (int nt = 0; nt < 16; nt++) {
                uint32_t b_off = (kt * 16 + lrow) * TSTRIDE + nt * 16;
                uint32_t bh0, bh1, bl0, bl1;
                ldsm_x2t(bh0, bh1, sbase + SM_WH + b_off);
                ldsm_x2t(bl0, bl1, sbase + SM_WL + b_off);
                mma16816(acc[nt], ah, bh0, bh1);   // Ah*Wh
                mma16816(acc[nt], ah, bl0, bl1);   // Ah*Wl
                mma16816(acc[nt], al, bh0, bh1);   // Al*Wh
            }
        }

        // ---- store D: groupID = lane>>2 (row), cols = (lane&3)*2
        int g   = lane >> 2;
        int cpo = (lane & 3) * 2;
        int r0  = row0 + wr + g;
        int r1  = r0 + 8;
        #pragma unroll
        for (int nt = 0; nt < 16; nt++) {
            int col = nt * 8 + cpo;
            if (r0 < N) {
                float2 o; o.x = acc[nt][0]; o.y = acc[nt][1];
                *(float2*)&g_x[(size_t)r0 * DD + col] = o;
            }
            if (r1 < N) {
                float2 o; o.x = acc[nt][2]; o.y = acc[nt][3];
                *(float2*)&g_x[(size_t)r1 * DD + col] = o;
            }
        }
        __syncthreads();   // protect A smem before next tile's stores
    }
}

// ---------------------------------------------------------------------------
// Fused aggregate + epilogue: one warp per node. (L2-gather bound)
// ---------------------------------------------------------------------------
__global__ void agg_kernel(float* __restrict__ out,
                           const float* __restrict__ bvec,
                           const float* __restrict__ prelu_a,
                           const float* __restrict__ gamma,
                           const float* __restrict__ beta,
                           int N)
{
    int gtid = blockIdx.x * blockDim.x + threadIdx.x;
    int i    = gtid >> 5;
    int lane = gtid & 31;
    if (i >= N) return;

    float di    = g_dis[i];
    int   start = g_row[i];
    int   len   = g_cnt[i];

    // self loop
    float4 xv = ((const float4*)g_x)[(size_t)i * 32 + lane];
    float  d2 = di * di;
    float a0 = d2 * xv.x, a1 = d2 * xv.y, a2 = d2 * xv.z, a3 = d2 * xv.w;

    for (int k = 0; k < len; k++) {
        int   s    = g_csr[start + k];
        float norm = di * g_dis[s];
        float4 v = ((const float4*)g_x)[(size_t)s * 32 + lane];
        a0 = fmaf(norm, v.x, a0);
        a1 = fmaf(norm, v.y, a1);
        a2 = fmaf(norm, v.z, a2);
        a3 = fmaf(norm, v.w, a3);
    }

    float4 bv = ((const float4*)bvec)[lane];
    float slope = prelu_a[0];

    float h0 = a0 + bv.x, h1 = a1 + bv.y, h2 = a2 + bv.z, h3 = a3 + bv.w;
    h0 = (h0 >= 0.f) ? h0 : slope * h0;
    h1 = (h1 >= 0.f) ? h1 : slope * h1;
    h2 = (h2 >= 0.f) ? h2 : slope * h2;
    h3 = (h3 >= 0.f) ? h3 : slope * h3;

    float sum = h0 + h1 + h2 + h3;
    float sq  = h0*h0 + h1*h1 + h2*h2 + h3*h3;
    #pragma unroll
    for (int m = 16; m > 0; m >>= 1) {
        sum += __shfl_xor_sync(0xFFFFFFFFu, sum, m);
        sq  += __shfl_xor_sync(0xFFFFFFFFu, sq,  m);
    }
    float mu   = sum * (1.0f / 128.0f);
    float var  = sq * (1.0f / 128.0f) - mu * mu;
    float rstd = rsqrtf(var + 1e-5f);

    float4 gm = ((const float4*)gamma)[lane];
    float4 be = ((const float4*)beta)[lane];

    float4 o;
    o.x = (h0 - mu) * rstd * gm.x + be.x;
    o.y = (h1 - mu) * rstd * gm.y + be.y;
    o.z = (h2 - mu) * rstd * gm.z + be.z;
    o.w = (h3 - mu) * rstd * gm.w + be.w;

    ((float4*)out)[(size_t)i * 32 + lane] = o;
}

// ---------------------------------------------------------------------------
extern "C" void kernel_launch(void* const* d_in, const int* in_sizes, int n_in,
                              void* d_out, int out_size)
{
    const float* h_in  = (const float*)d_in[0];
    const int*   ei    = (const int*)d_in[1];     // int32 (JAX default x64 off)
    const float* W     = (const float*)d_in[2];
    const float* bvec  = (const float*)d_in[3];
    const float* pa    = (const float*)d_in[4];
    const float* gamma = (const float*)d_in[5];
    const float* beta  = (const float*)d_in[6];
    float*       out   = (float*)d_out;

    int N = in_sizes[0] / DD;
    int E = in_sizes[1] / 2;
    if (N > NMAX) N = NMAX;
    if (E > EMAX) E = EMAX;

    int nb1024 = (N + 1023) / 1024;

    cudaFuncSetAttribute(gemm_tc, cudaFuncAttributeMaxDynamicSharedMemorySize,
                         SMEM_DYN);

    // CSR build
    zero_kernel<<<(N + 255) / 256, 256>>>(N);
    count_kernel<<<(E + 255) / 256, 256>>>(ei, E);
    scan_block<<<nb1024, 1024>>>(N);
    scan_part<<<1, 1024>>>(nb1024);
    scan_add<<<nb1024, 1024>>>(N);
    fill_kernel<<<(E + 255) / 256, 256>>>(ei, E);

    // GEMM (HMMA bf16-split)
    gemm_tc<<<148, 256, SMEM_DYN>>>(h_in, W, N);

    // Fused aggregate + bias + PReLU + LayerNorm
    {
        int threads = N * 32;
        agg_kernel<<<(threads + 255) / 256, 256>>>(out, bvec, pa, gamma, beta, N);
    }
}